// round 7
// baseline (speedup 1.0000x reference)
#include <cuda_runtime.h>
#include <cstdint>

// Problem dims (fixed)
#define B_  16
#define U_  64
#define T_  128
#define E_  128
#define HID_ 256
#define H_  4
#define ENC_H_ 128
#define IN_DIM_ 32

typedef unsigned long long ull;

// Scratch (device globals: no allocation allowed)
__device__ float g_qu[B_ * U_ * HID_];    // ue @ fw1[:E]          (1024 x 256)
__device__ float g_kh[B_ * T_ * HID_];    // te @ fw1[E:]          (2048 x 256)
__device__ float g_qb[H_ * HID_];         // head_q @ fw1[:E] + fb1 (4 x 256)
__device__ float g_part[4][B_ * H_ * U_ * T_];  // d-quadrant partial sums

// ---- packed f32x2 helpers (Blackwell) ----
__device__ __forceinline__ ull add2(ull a, ull b) {
    ull r;
    asm("add.rn.f32x2 %0, %1, %2;" : "=l"(r) : "l"(a), "l"(b));
    return r;
}
__device__ __forceinline__ void fma2(ull& acc, ull a, ull b) {
    asm("fma.rn.f32x2 %0, %1, %2, %0;" : "+l"(acc) : "l"(a), "l"(b));
}
__device__ __forceinline__ ull relu2(ull x) {
    float lo, hi;
    asm("mov.b64 {%0,%1}, %2;" : "=f"(lo), "=f"(hi) : "l"(x));
    lo = fmaxf(lo, 0.f);
    hi = fmaxf(hi, 0.f);
    ull r;
    asm("mov.b64 %0, {%1,%2};" : "=l"(r) : "f"(lo), "f"(hi));
    return r;
}
__device__ __forceinline__ float hsum2(ull x) {
    float lo, hi;
    asm("mov.b64 {%0,%1}, %2;" : "=f"(lo), "=f"(hi) : "l"(x));
    return lo + hi;
}

// ---------------------------------------------------------------------------
// Encoder GEMM micro-step: 2 rows x 4 cols x 4 k per call.
// a0p/a1p: pointers to 4 consecutive k-activations of the two rows (smem,
// warp-uniform -> broadcast). wp: &W[k][col], ldw = output width of W.
// ---------------------------------------------------------------------------
__device__ __forceinline__ void acc_step(
    float acc[2][4], const float* a0p, const float* a1p,
    const float* __restrict__ wp, int ldw)
{
    float4 a0 = *(const float4*)a0p;
    float4 a1 = *(const float4*)a1p;
    float4 w0 = __ldg((const float4*)(wp));
    float4 w1 = __ldg((const float4*)(wp + ldw));
    float4 w2 = __ldg((const float4*)(wp + 2 * ldw));
    float4 w3 = __ldg((const float4*)(wp + 3 * ldw));
#define ESTEP(r, aR) \
    acc[r][0] = fmaf(aR.x, w0.x, fmaf(aR.y, w1.x, fmaf(aR.z, w2.x, fmaf(aR.w, w3.x, acc[r][0])))); \
    acc[r][1] = fmaf(aR.x, w0.y, fmaf(aR.y, w1.y, fmaf(aR.z, w2.y, fmaf(aR.w, w3.y, acc[r][1])))); \
    acc[r][2] = fmaf(aR.x, w0.z, fmaf(aR.y, w1.z, fmaf(aR.z, w2.z, fmaf(aR.w, w3.z, acc[r][2])))); \
    acc[r][3] = fmaf(aR.x, w0.w, fmaf(aR.y, w1.w, fmaf(aR.z, w2.w, fmaf(aR.w, w3.w, acc[r][3]))));
    ESTEP(0, a0)
    ESTEP(1, a1)
#undef ESTEP
}

// ---------------------------------------------------------------------------
// Fused encoder: blocks [0,64) = UAV (16 rows each), [64,192) = task,
// block 192 = qb.  256 threads: cg = tid&31 -> cols 4cg..4cg+3,
// rg = tid>>5 -> rows 2rg, 2rg+1.  Warp = fixed rg -> activation loads
// warp-uniform (broadcast), weight loads LDG.128 coalesced.
// ---------------------------------------------------------------------------
__global__ __launch_bounds__(256) void enc_fused_kernel(
    const float* __restrict__ uav_feat, const float* __restrict__ task_feat,
    const float* __restrict__ uw0, const float* __restrict__ ub0,
    const float* __restrict__ uw1, const float* __restrict__ ub1,
    const float* __restrict__ uw2, const float* __restrict__ ub2,
    const float* __restrict__ tw0, const float* __restrict__ tb0,
    const float* __restrict__ tw1, const float* __restrict__ tb1,
    const float* __restrict__ tw2, const float* __restrict__ tb2,
    const float* __restrict__ head_q, const float* __restrict__ fw1,
    const float* __restrict__ fb1)
{
    const int bx = blockIdx.x;
    const int tid = threadIdx.x;

    // ---------------- qb block ----------------
    if (bx == 192) {
        int d = tid;   // 0..255
        #pragma unroll
        for (int h = 0; h < H_; ++h) {
            float acc = fb1[d];
            #pragma unroll 8
            for (int k = 0; k < E_; ++k)
                acc += head_q[h * E_ + k] * fw1[k * HID_ + d];
            g_qb[h * HID_ + d] = acc;
        }
        return;
    }

    const int is_task = (bx >= 64);
    const float* x  = is_task ? task_feat : uav_feat;
    const float* w0 = is_task ? tw0 : uw0;
    const float* b0 = is_task ? tb0 : ub0;
    const float* w1 = is_task ? tw1 : uw1;
    const float* b1 = is_task ? tb1 : ub1;
    const float* w2 = is_task ? tw2 : uw2;
    const float* b2 = is_task ? tb2 : ub2;
    float* out      = is_task ? g_kh : g_qu;
    const int fw1_off = is_task ? E_ : 0;
    const int row0 = (is_task ? (bx - 64) : bx) * 16;

    __shared__ float xs[16][IN_DIM_];
    __shared__ float bufA[16][ENC_H_];
    __shared__ float bufB[16][ENC_H_];

    // load 16x32 input tile
    for (int i = tid; i < 16 * IN_DIM_; i += 256)
        xs[i >> 5][i & 31] = x[(row0 + (i >> 5)) * IN_DIM_ + (i & 31)];
    __syncthreads();

    const int cg = tid & 31;       // col group: cols 4cg..4cg+3
    const int r0 = (tid >> 5) * 2; // rows r0, r0+1
    const int col = cg * 4;
    float acc[2][4];

    // ---- layer 0: 32 -> 128, relu ----
    {
        float4 bv = __ldg((const float4*)(b0 + col));
        acc[0][0] = bv.x; acc[0][1] = bv.y; acc[0][2] = bv.z; acc[0][3] = bv.w;
        acc[1][0] = bv.x; acc[1][1] = bv.y; acc[1][2] = bv.z; acc[1][3] = bv.w;
        #pragma unroll
        for (int k = 0; k < IN_DIM_; k += 4)
            acc_step(acc, &xs[r0][k], &xs[r0 + 1][k],
                     w0 + k * ENC_H_ + col, ENC_H_);
        #pragma unroll
        for (int r = 0; r < 2; ++r) {
            float4 v = make_float4(fmaxf(acc[r][0], 0.f), fmaxf(acc[r][1], 0.f),
                                   fmaxf(acc[r][2], 0.f), fmaxf(acc[r][3], 0.f));
            *(float4*)&bufA[r0 + r][col] = v;
        }
    }
    __syncthreads();

    // ---- layer 1: 128 -> 128, relu ----
    {
        float4 bv = __ldg((const float4*)(b1 + col));
        acc[0][0] = bv.x; acc[0][1] = bv.y; acc[0][2] = bv.z; acc[0][3] = bv.w;
        acc[1][0] = bv.x; acc[1][1] = bv.y; acc[1][2] = bv.z; acc[1][3] = bv.w;
        #pragma unroll 8
        for (int k = 0; k < ENC_H_; k += 4)
            acc_step(acc, &bufA[r0][k], &bufA[r0 + 1][k],
                     w1 + k * ENC_H_ + col, ENC_H_);
        #pragma unroll
        for (int r = 0; r < 2; ++r) {
            float4 v = make_float4(fmaxf(acc[r][0], 0.f), fmaxf(acc[r][1], 0.f),
                                   fmaxf(acc[r][2], 0.f), fmaxf(acc[r][3], 0.f));
            *(float4*)&bufB[r0 + r][col] = v;
        }
    }
    __syncthreads();

    // ---- layer 2: 128 -> 128 (no relu) ----
    {
        float4 bv = __ldg((const float4*)(b2 + col));
        acc[0][0] = bv.x; acc[0][1] = bv.y; acc[0][2] = bv.z; acc[0][3] = bv.w;
        acc[1][0] = bv.x; acc[1][1] = bv.y; acc[1][2] = bv.z; acc[1][3] = bv.w;
        #pragma unroll 8
        for (int k = 0; k < ENC_H_; k += 4)
            acc_step(acc, &bufB[r0][k], &bufB[r0 + 1][k],
                     w2 + k * ENC_H_ + col, ENC_H_);
    }
    __syncthreads();   // bufA reads done
    #pragma unroll
    for (int r = 0; r < 2; ++r)
        *(float4*)&bufA[r0 + r][col] = make_float4(acc[r][0], acc[r][1],
                                                   acc[r][2], acc[r][3]);
    __syncthreads();

    // ---- projection through fw1 slice: 128 -> 256 ----
    const float* wp = fw1 + fw1_off * HID_;
    #pragma unroll
    for (int p = 0; p < 2; ++p) {
        int pc = col + p * 128;
        #pragma unroll
        for (int r = 0; r < 2; ++r)
            acc[r][0] = acc[r][1] = acc[r][2] = acc[r][3] = 0.f;
        #pragma unroll 8
        for (int k = 0; k < E_; k += 4)
            acc_step(acc, &bufA[r0][k], &bufA[r0 + 1][k],
                     wp + k * HID_ + pc, HID_);
        #pragma unroll
        for (int r = 0; r < 2; ++r)
            *(float4*)&out[(size_t)(row0 + r0 + r) * HID_ + pc] =
                make_float4(acc[r][0], acc[r][1], acc[r][2], acc[r][3]);
    }
}

// ---------------------------------------------------------------------------
// Stage E (d-split): partial[dq][z][u][t] =
//   sum_{d in quad} relu(qu[b,u,d]+qb[h,d]+kh[b,t,d]) * fw2[d]
// Block: (dq, z). Tile 64u x 128t x 64d, 512 threads, thread tile 4u x 4t.
// tg = tid&31 -> t = tg + 32*jj;  ug = tid>>5 -> u = 4*ug + i.
// q/w loads warp-uniform (broadcast); k loads conflict-free (stride 68).
// ---------------------------------------------------------------------------
#define DQ 64                      // d per quadrant
#define QSTRIDE 68                 // 64 + 4 pad (4*17, odd*4 -> conflict-free)
#define SMEM_E_FLOATS (64 * QSTRIDE + 128 * QSTRIDE + DQ)
#define SMEM_E_BYTES  (SMEM_E_FLOATS * 4)

__global__ __launch_bounds__(512, 2) void stageE_kernel()
{
    extern __shared__ float smem[];
    float* qs   = smem;                        // [64][68]
    float* ks   = smem + 64 * QSTRIDE;         // [128][68]
    float* fw2s = ks + 128 * QSTRIDE;          // [64]  (filled by launch arg copy below)

    const int tid = threadIdx.x;
    const int dq  = blockIdx.x;               // 0..3
    const int z   = blockIdx.y;               // b*H + h
    const int b   = z >> 2;
    const int h   = z & 3;
    const int d0  = dq * DQ;

    // --- fill qs[u][dl] = qu + qb ---
    {
        const float4* qb4 = (const float4*)(g_qb + h * HID_ + d0);
        #pragma unroll
        for (int p = 0; p < 2; ++p) {
            int idx = tid + p * 512;          // 1024 float4s
            int u   = idx >> 4;
            int d4  = idx & 15;
            float4 a = ((const float4*)(g_qu + (size_t)(b * U_ + u) * HID_ + d0))[d4];
            float4 qb = qb4[d4];
            a.x += qb.x; a.y += qb.y; a.z += qb.z; a.w += qb.w;
            ((float4*)(qs + u * QSTRIDE))[d4] = a;
        }
    }
    // --- fill ks[t][dl] ---
    {
        #pragma unroll
        for (int p = 0; p < 4; ++p) {
            int idx = tid + p * 512;          // 2048 float4s
            int t   = idx >> 4;
            int d4  = idx & 15;
            ((float4*)(ks + t * QSTRIDE))[d4] =
                ((const float4*)(g_kh + (size_t)(b * T_ + t) * HID_ + d0))[d4];
        }
    }
    __syncthreads();

    const int tg = tid & 31;       // t = tg + 32*jj
    const int ug = tid >> 5;       // u = 4*ug + i   (warp-uniform)

    ull acc[4][4];
    #pragma unroll
    for (int i = 0; i < 4; ++i)
        #pragma unroll
        for (int jj = 0; jj < 4; ++jj) acc[i][jj] = 0ULL;

    const float* qbase = qs + (ug * 4) * QSTRIDE;
    const float* kbase = ks + tg * QSTRIDE;

    #pragma unroll 4
    for (int d4 = 0; d4 < DQ / 4; ++d4) {
        ulonglong2 wv = *(const ulonglong2*)(fw2s + d4 * 4);
        ulonglong2 qv[4], kv[4];
        #pragma unroll
        for (int i = 0; i < 4; ++i)
            qv[i] = *(const ulonglong2*)(qbase + i * QSTRIDE + d4 * 4);
        #pragma unroll
        for (int jj = 0; jj < 4; ++jj)
            kv[jj] = *(const ulonglong2*)(kbase + jj * 32 * QSTRIDE + d4 * 4);

        #pragma unroll
        for (int i = 0; i < 4; ++i) {
            #pragma unroll
            for (int jj = 0; jj < 4; ++jj) {
                fma2(acc[i][jj], relu2(add2(qv[i].x, kv[jj].x)), wv.x);
                fma2(acc[i][jj], relu2(add2(qv[i].y, kv[jj].y)), wv.y);
            }
        }
    }

    float* part = g_part[dq] + (size_t)z * U_ * T_;
    #pragma unroll
    for (int i = 0; i < 4; ++i) {
        float* row = part + (ug * 4 + i) * T_ + tg;
        #pragma unroll
        for (int jj = 0; jj < 4; ++jj)
            row[jj * 32] = hsum2(acc[i][jj]);
    }
}

// fw2 staging into stageE's smem tail: done inside stageE via global read.
// (fw2s fill kernel-side — small helper executed by first 16 threads.)
__global__ __launch_bounds__(512, 2) void stageE_full_kernel(
    const float* __restrict__ fw2);

// Actual stageE with fw2 parameter (replaces placeholder above).
__global__ __launch_bounds__(512, 2) void stageE_k(
    const float* __restrict__ fw2)
{
    extern __shared__ float smem[];
    float* qs   = smem;
    float* ks   = smem + 64 * QSTRIDE;
    float* fw2s = ks + 128 * QSTRIDE;

    const int tid = threadIdx.x;
    const int dq  = blockIdx.x;
    const int z   = blockIdx.y;
    const int b   = z >> 2;
    const int h   = z & 3;
    const int d0  = dq * DQ;

    if (tid < DQ / 4)
        ((float4*)fw2s)[tid] = ((const float4*)(fw2 + d0))[tid];

    {
        const float4* qb4 = (const float4*)(g_qb + h * HID_ + d0);
        #pragma unroll
        for (int p = 0; p < 2; ++p) {
            int idx = tid + p * 512;
            int u   = idx >> 4;
            int d4  = idx & 15;
            float4 a = ((const float4*)(g_qu + (size_t)(b * U_ + u) * HID_ + d0))[d4];
            float4 qb = qb4[d4];
            a.x += qb.x; a.y += qb.y; a.z += qb.z; a.w += qb.w;
            ((float4*)(qs + u * QSTRIDE))[d4] = a;
        }
    }
    {
        #pragma unroll
        for (int p = 0; p < 4; ++p) {
            int idx = tid + p * 512;
            int t   = idx >> 4;
            int d4  = idx & 15;
            ((float4*)(ks + t * QSTRIDE))[d4] =
                ((const float4*)(g_kh + (size_t)(b * T_ + t) * HID_ + d0))[d4];
        }
    }
    __syncthreads();

    const int tg = tid & 31;
    const int ug = tid >> 5;

    ull acc[4][4];
    #pragma unroll
    for (int i = 0; i < 4; ++i)
        #pragma unroll
        for (int jj = 0; jj < 4; ++jj) acc[i][jj] = 0ULL;

    const float* qbase = qs + (ug * 4) * QSTRIDE;
    const float* kbase = ks + tg * QSTRIDE;

    #pragma unroll 4
    for (int d4 = 0; d4 < DQ / 4; ++d4) {
        ulonglong2 wv = *(const ulonglong2*)(fw2s + d4 * 4);
        ulonglong2 qv[4], kv[4];
        #pragma unroll
        for (int i = 0; i < 4; ++i)
            qv[i] = *(const ulonglong2*)(qbase + i * QSTRIDE + d4 * 4);
        #pragma unroll
        for (int jj = 0; jj < 4; ++jj)
            kv[jj] = *(const ulonglong2*)(kbase + jj * 32 * QSTRIDE + d4 * 4);

        #pragma unroll
        for (int i = 0; i < 4; ++i) {
            #pragma unroll
            for (int jj = 0; jj < 4; ++jj) {
                fma2(acc[i][jj], relu2(add2(qv[i].x, kv[jj].x)), wv.x);
                fma2(acc[i][jj], relu2(add2(qv[i].y, kv[jj].y)), wv.y);
            }
        }
    }

    float* part = g_part[dq] + (size_t)z * U_ * T_;
    #pragma unroll
    for (int i = 0; i < 4; ++i) {
        float* row = part + (ug * 4 + i) * T_ + tg;
        #pragma unroll
        for (int jj = 0; jj < 4; ++jj)
            row[jj * 32] = hsum2(acc[i][jj]);
    }
}

// Unused placeholder definitions (keep linker happy)
__global__ __launch_bounds__(512, 2) void stageE_kernel_unused() {}
__global__ __launch_bounds__(512, 2) void stageE_full_kernel(
    const float* __restrict__ fw2) { (void)fw2; }

// ---------------------------------------------------------------------------
// Combine: out = sum of 4 d-quadrant partials + fb2
// ---------------------------------------------------------------------------
__global__ __launch_bounds__(256) void combine_kernel(
    float* __restrict__ out, const float* __restrict__ fb2)
{
    const float bias = fb2[0];
    int i = blockIdx.x * 256 + threadIdx.x;      // float4 index, 131072 total
    float4 a = ((const float4*)g_part[0])[i];
    float4 b = ((const float4*)g_part[1])[i];
    float4 c = ((const float4*)g_part[2])[i];
    float4 d = ((const float4*)g_part[3])[i];
    float4 r;
    r.x = a.x + b.x + c.x + d.x + bias;
    r.y = a.y + b.y + c.y + d.y + bias;
    r.z = a.z + b.z + c.z + d.z + bias;
    r.w = a.w + b.w + c.w + d.w + bias;
    ((float4*)out)[i] = r;
}

// ---------------------------------------------------------------------------
extern "C" void kernel_launch(void* const* d_in, const int* in_sizes, int n_in,
                              void* d_out, int out_size)
{
    const float* uav_feat = (const float*)d_in[0];
    const float* task_feat = (const float*)d_in[1];
    const float* uw0 = (const float*)d_in[2];
    const float* ub0 = (const float*)d_in[3];
    const float* uw1 = (const float*)d_in[4];
    const float* ub1 = (const float*)d_in[5];
    const float* uw2 = (const float*)d_in[6];
    const float* ub2 = (const float*)d_in[7];
    const float* tw0 = (const float*)d_in[8];
    const float* tb0 = (const float*)d_in[9];
    const float* tw1 = (const float*)d_in[10];
    const float* tb1 = (const float*)d_in[11];
    const float* tw2 = (const float*)d_in[12];
    const float* tb2 = (const float*)d_in[13];
    const float* head_q = (const float*)d_in[14];
    const float* fw1 = (const float*)d_in[15];
    const float* fb1 = (const float*)d_in[16];
    const float* fw2 = (const float*)d_in[17];
    const float* fb2 = (const float*)d_in[18];
    float* out = (float*)d_out;

    cudaFuncSetAttribute(stageE_k,
                         cudaFuncAttributeMaxDynamicSharedMemorySize,
                         SMEM_E_BYTES);

    // Encoders + qb in one launch (193 blocks x 256 threads)
    enc_fused_kernel<<<193, 256>>>(uav_feat, task_feat,
                                   uw0, ub0, uw1, ub1, uw2, ub2,
                                   tw0, tb0, tw1, tb1, tw2, tb2,
                                   head_q, fw1, fb1);

    // Stage E over 4 d-quadrants x 64 (b,h)
    dim3 grid(4, B_ * H_);
    stageE_k<<<grid, 512, SMEM_E_BYTES>>>(fw2);

    // Combine partials + bias
    combine_kernel<<<(B_ * H_ * U_ * T_ / 4) / 256, 256>>>(out, fb2);
}

// round 8
// speedup vs baseline: 1.0052x; 1.0052x over previous
#include <cuda_runtime.h>
#include <cstdint>

// Problem dims (fixed)
#define B_  16
#define U_  64
#define T_  128
#define E_  128
#define HID_ 256
#define H_  4
#define ENC_H_ 128
#define IN_DIM_ 32

typedef unsigned long long ull;

// Scratch (device globals: no allocation allowed)
__device__ float g_qu[B_ * U_ * HID_];    // ue @ fw1[:E]          (1024 x 256)
__device__ float g_kh[B_ * T_ * HID_];    // te @ fw1[E:]          (2048 x 256)
__device__ float g_qb[H_ * HID_];         // head_q @ fw1[:E] + fb1 (4 x 256)
__device__ float g_part[4][B_ * H_ * U_ * T_];  // d-quadrant partial sums

// ---- packed f32x2 helpers (Blackwell) ----
__device__ __forceinline__ ull add2(ull a, ull b) {
    ull r;
    asm("add.rn.f32x2 %0, %1, %2;" : "=l"(r) : "l"(a), "l"(b));
    return r;
}
__device__ __forceinline__ void fma2(ull& acc, ull a, ull b) {
    asm("fma.rn.f32x2 %0, %1, %2, %0;" : "+l"(acc) : "l"(a), "l"(b));
}
__device__ __forceinline__ ull relu2(ull x) {
    float lo, hi;
    asm("mov.b64 {%0,%1}, %2;" : "=f"(lo), "=f"(hi) : "l"(x));
    lo = fmaxf(lo, 0.f);
    hi = fmaxf(hi, 0.f);
    ull r;
    asm("mov.b64 %0, {%1,%2};" : "=l"(r) : "f"(lo), "f"(hi));
    return r;
}
__device__ __forceinline__ float hsum2(ull x) {
    float lo, hi;
    asm("mov.b64 {%0,%1}, %2;" : "=f"(lo), "=f"(hi) : "l"(x));
    return lo + hi;
}

// ---------------------------------------------------------------------------
// Encoder macro-step: 1 row x 4 cols x 8 k.  Loads batched (8 LDG.128 +
// 2 LDS.128) before 32 FFMA so ptxas issues them as an MLP front-batch.
// ap: &act[row][k] (smem, warp-uniform -> broadcast); wp: &W[k][col].
// ---------------------------------------------------------------------------
__device__ __forceinline__ void acc_step8(
    float acc[4], const float* ap, const float* __restrict__ wp, int ldw)
{
    float4 a0 = *(const float4*)ap;
    float4 a1 = *(const float4*)(ap + 4);
    float4 w[8];
    #pragma unroll
    for (int q = 0; q < 8; ++q)
        w[q] = __ldg((const float4*)(wp + q * ldw));
    acc[0] = fmaf(a0.x, w[0].x, acc[0]); acc[1] = fmaf(a0.x, w[0].y, acc[1]);
    acc[2] = fmaf(a0.x, w[0].z, acc[2]); acc[3] = fmaf(a0.x, w[0].w, acc[3]);
    acc[0] = fmaf(a0.y, w[1].x, acc[0]); acc[1] = fmaf(a0.y, w[1].y, acc[1]);
    acc[2] = fmaf(a0.y, w[1].z, acc[2]); acc[3] = fmaf(a0.y, w[1].w, acc[3]);
    acc[0] = fmaf(a0.z, w[2].x, acc[0]); acc[1] = fmaf(a0.z, w[2].y, acc[1]);
    acc[2] = fmaf(a0.z, w[2].z, acc[2]); acc[3] = fmaf(a0.z, w[2].w, acc[3]);
    acc[0] = fmaf(a0.w, w[3].x, acc[0]); acc[1] = fmaf(a0.w, w[3].y, acc[1]);
    acc[2] = fmaf(a0.w, w[3].z, acc[2]); acc[3] = fmaf(a0.w, w[3].w, acc[3]);
    acc[0] = fmaf(a1.x, w[4].x, acc[0]); acc[1] = fmaf(a1.x, w[4].y, acc[1]);
    acc[2] = fmaf(a1.x, w[4].z, acc[2]); acc[3] = fmaf(a1.x, w[4].w, acc[3]);
    acc[0] = fmaf(a1.y, w[5].x, acc[0]); acc[1] = fmaf(a1.y, w[5].y, acc[1]);
    acc[2] = fmaf(a1.y, w[5].z, acc[2]); acc[3] = fmaf(a1.y, w[5].w, acc[3]);
    acc[0] = fmaf(a1.z, w[6].x, acc[0]); acc[1] = fmaf(a1.z, w[6].y, acc[1]);
    acc[2] = fmaf(a1.z, w[6].z, acc[2]); acc[3] = fmaf(a1.z, w[6].w, acc[3]);
    acc[0] = fmaf(a1.w, w[7].x, acc[0]); acc[1] = fmaf(a1.w, w[7].y, acc[1]);
    acc[2] = fmaf(a1.w, w[7].z, acc[2]); acc[3] = fmaf(a1.w, w[7].w, acc[3]);
}

// ---------------------------------------------------------------------------
// Fused encoder: blocks [0,128) = UAV (8 rows each), [128,384) = task,
// block 384 = qb.  256 threads: cg = tid&31 -> cols 4cg..4cg+3,
// row = tid>>5 (8 rows, one per warp).  Activation loads warp-uniform
// (broadcast), weight loads LDG.128 coalesced (warp covers a full W row).
// ---------------------------------------------------------------------------
#define ENC_ROWS 8

__global__ __launch_bounds__(256) void enc_fused_kernel(
    const float* __restrict__ uav_feat, const float* __restrict__ task_feat,
    const float* __restrict__ uw0, const float* __restrict__ ub0,
    const float* __restrict__ uw1, const float* __restrict__ ub1,
    const float* __restrict__ uw2, const float* __restrict__ ub2,
    const float* __restrict__ tw0, const float* __restrict__ tb0,
    const float* __restrict__ tw1, const float* __restrict__ tb1,
    const float* __restrict__ tw2, const float* __restrict__ tb2,
    const float* __restrict__ head_q, const float* __restrict__ fw1,
    const float* __restrict__ fb1)
{
    const int bx = blockIdx.x;
    const int tid = threadIdx.x;

    // ---------------- qb block ----------------
    if (bx == 384) {
        int d = tid;   // 0..255
        #pragma unroll
        for (int h = 0; h < H_; ++h) {
            float acc = fb1[d];
            #pragma unroll 8
            for (int k = 0; k < E_; ++k)
                acc += head_q[h * E_ + k] * fw1[k * HID_ + d];
            g_qb[h * HID_ + d] = acc;
        }
        return;
    }

    const int is_task = (bx >= 128);
    const float* x  = is_task ? task_feat : uav_feat;
    const float* w0 = is_task ? tw0 : uw0;
    const float* b0 = is_task ? tb0 : ub0;
    const float* w1 = is_task ? tw1 : uw1;
    const float* b1 = is_task ? tb1 : ub1;
    const float* w2 = is_task ? tw2 : uw2;
    const float* b2 = is_task ? tb2 : ub2;
    float* out      = is_task ? g_kh : g_qu;
    const int fw1_off = is_task ? E_ : 0;
    const int row0 = (is_task ? (bx - 128) : bx) * ENC_ROWS;

    __shared__ float xs[ENC_ROWS][IN_DIM_];
    __shared__ float bufA[ENC_ROWS][ENC_H_];
    __shared__ float bufB[ENC_ROWS][ENC_H_];

    // load 8x32 input tile
    if (tid < ENC_ROWS * IN_DIM_)
        xs[tid >> 5][tid & 31] = x[(row0 + (tid >> 5)) * IN_DIM_ + (tid & 31)];
    __syncthreads();

    const int cg  = tid & 31;        // cols 4cg..4cg+3
    const int row = tid >> 5;        // one row per warp
    const int col = cg * 4;
    float acc[4];

    // ---- layer 0: 32 -> 128, relu ----
    {
        float4 bv = __ldg((const float4*)(b0 + col));
        acc[0] = bv.x; acc[1] = bv.y; acc[2] = bv.z; acc[3] = bv.w;
        #pragma unroll
        for (int k = 0; k < IN_DIM_; k += 8)
            acc_step8(acc, &xs[row][k], w0 + k * ENC_H_ + col, ENC_H_);
        *(float4*)&bufA[row][col] = make_float4(
            fmaxf(acc[0], 0.f), fmaxf(acc[1], 0.f),
            fmaxf(acc[2], 0.f), fmaxf(acc[3], 0.f));
    }
    __syncthreads();

    // ---- layer 1: 128 -> 128, relu ----
    {
        float4 bv = __ldg((const float4*)(b1 + col));
        acc[0] = bv.x; acc[1] = bv.y; acc[2] = bv.z; acc[3] = bv.w;
        #pragma unroll
        for (int k = 0; k < ENC_H_; k += 8)
            acc_step8(acc, &bufA[row][k], w1 + k * ENC_H_ + col, ENC_H_);
        *(float4*)&bufB[row][col] = make_float4(
            fmaxf(acc[0], 0.f), fmaxf(acc[1], 0.f),
            fmaxf(acc[2], 0.f), fmaxf(acc[3], 0.f));
    }
    __syncthreads();

    // ---- layer 2: 128 -> 128 (no relu) ----
    {
        float4 bv = __ldg((const float4*)(b2 + col));
        acc[0] = bv.x; acc[1] = bv.y; acc[2] = bv.z; acc[3] = bv.w;
        #pragma unroll
        for (int k = 0; k < ENC_H_; k += 8)
            acc_step8(acc, &bufB[row][k], w2 + k * ENC_H_ + col, ENC_H_);
    }
    __syncthreads();   // bufA reads done
    *(float4*)&bufA[row][col] = make_float4(acc[0], acc[1], acc[2], acc[3]);
    __syncthreads();

    // ---- projection through fw1 slice: 128 -> 256 ----
    const float* wp = fw1 + fw1_off * HID_;
    #pragma unroll
    for (int p = 0; p < 2; ++p) {
        int pc = col + p * 128;
        acc[0] = acc[1] = acc[2] = acc[3] = 0.f;
        #pragma unroll
        for (int k = 0; k < E_; k += 8)
            acc_step8(acc, &bufA[row][k], wp + k * HID_ + pc, HID_);
        *(float4*)&out[(size_t)(row0 + row) * HID_ + pc] =
            make_float4(acc[0], acc[1], acc[2], acc[3]);
    }
}

// ---------------------------------------------------------------------------
// Stage E (d-split): partial[dq][z][u][t] =
//   sum_{d in quad} relu(qu[b,u,d]+qb[h,d]+kh[b,t,d]) * fw2[d]
// Block: (dq, z). Tile 64u x 128t x 64d, 512 threads, thread tile 4u x 4t.
// tg = tid&31 -> t = tg + 32*jj;  ug = tid>>5 -> u = 4*ug + i (warp-uniform).
// q/w loads broadcast; k loads conflict-free (stride 68).
// ---------------------------------------------------------------------------
#define DQ 64
#define QSTRIDE 68
#define SMEM_E_FLOATS (64 * QSTRIDE + 128 * QSTRIDE + DQ)
#define SMEM_E_BYTES  (SMEM_E_FLOATS * 4)

__global__ __launch_bounds__(512, 2) void stageE_k(
    const float* __restrict__ fw2)
{
    extern __shared__ float smem[];
    float* qs   = smem;                        // [64][68]
    float* ks   = smem + 64 * QSTRIDE;         // [128][68]
    float* fw2s = ks + 128 * QSTRIDE;          // [64]

    const int tid = threadIdx.x;
    const int dq  = blockIdx.x;               // 0..3
    const int z   = blockIdx.y;               // b*H + h
    const int b   = z >> 2;
    const int h   = z & 3;
    const int d0  = dq * DQ;

    if (tid < DQ / 4)
        ((float4*)fw2s)[tid] = ((const float4*)(fw2 + d0))[tid];

    {
        const float4* qb4 = (const float4*)(g_qb + h * HID_ + d0);
        #pragma unroll
        for (int p = 0; p < 2; ++p) {
            int idx = tid + p * 512;
            int u   = idx >> 4;
            int d4  = idx & 15;
            float4 a = ((const float4*)(g_qu + (size_t)(b * U_ + u) * HID_ + d0))[d4];
            float4 qb = qb4[d4];
            a.x += qb.x; a.y += qb.y; a.z += qb.z; a.w += qb.w;
            ((float4*)(qs + u * QSTRIDE))[d4] = a;
        }
    }
    {
        #pragma unroll
        for (int p = 0; p < 4; ++p) {
            int idx = tid + p * 512;
            int t   = idx >> 4;
            int d4  = idx & 15;
            ((float4*)(ks + t * QSTRIDE))[d4] =
                ((const float4*)(g_kh + (size_t)(b * T_ + t) * HID_ + d0))[d4];
        }
    }
    __syncthreads();

    const int tg = tid & 31;       // t = tg + 32*jj
    const int ug = tid >> 5;       // u = 4*ug + i

    ull acc[4][4];
    #pragma unroll
    for (int i = 0; i < 4; ++i)
        #pragma unroll
        for (int jj = 0; jj < 4; ++jj) acc[i][jj] = 0ULL;

    const float* qbase = qs + (ug * 4) * QSTRIDE;
    const float* kbase = ks + tg * QSTRIDE;

    #pragma unroll 4
    for (int d4 = 0; d4 < DQ / 4; ++d4) {
        ulonglong2 wv = *(const ulonglong2*)(fw2s + d4 * 4);
        ulonglong2 qv[4], kv[4];
        #pragma unroll
        for (int i = 0; i < 4; ++i)
            qv[i] = *(const ulonglong2*)(qbase + i * QSTRIDE + d4 * 4);
        #pragma unroll
        for (int jj = 0; jj < 4; ++jj)
            kv[jj] = *(const ulonglong2*)(kbase + jj * 32 * QSTRIDE + d4 * 4);

        #pragma unroll
        for (int i = 0; i < 4; ++i) {
            #pragma unroll
            for (int jj = 0; jj < 4; ++jj) {
                fma2(acc[i][jj], relu2(add2(qv[i].x, kv[jj].x)), wv.x);
                fma2(acc[i][jj], relu2(add2(qv[i].y, kv[jj].y)), wv.y);
            }
        }
    }

    float* part = g_part[dq] + (size_t)z * U_ * T_;
    #pragma unroll
    for (int i = 0; i < 4; ++i) {
        float* row = part + (ug * 4 + i) * T_ + tg;
        #pragma unroll
        for (int jj = 0; jj < 4; ++jj)
            row[jj * 32] = hsum2(acc[i][jj]);
    }
}

// ---------------------------------------------------------------------------
// Combine: out = sum of 4 d-quadrant partials + fb2
// ---------------------------------------------------------------------------
__global__ __launch_bounds__(256) void combine_kernel(
    float* __restrict__ out, const float* __restrict__ fb2)
{
    const float bias = fb2[0];
    int i = blockIdx.x * 256 + threadIdx.x;      // float4 index, 131072 total
    float4 a = ((const float4*)g_part[0])[i];
    float4 b = ((const float4*)g_part[1])[i];
    float4 c = ((const float4*)g_part[2])[i];
    float4 d = ((const float4*)g_part[3])[i];
    float4 r;
    r.x = a.x + b.x + c.x + d.x + bias;
    r.y = a.y + b.y + c.y + d.y + bias;
    r.z = a.z + b.z + c.z + d.z + bias;
    r.w = a.w + b.w + c.w + d.w + bias;
    ((float4*)out)[i] = r;
}

// ---------------------------------------------------------------------------
extern "C" void kernel_launch(void* const* d_in, const int* in_sizes, int n_in,
                              void* d_out, int out_size)
{
    const float* uav_feat = (const float*)d_in[0];
    const float* task_feat = (const float*)d_in[1];
    const float* uw0 = (const float*)d_in[2];
    const float* ub0 = (const float*)d_in[3];
    const float* uw1 = (const float*)d_in[4];
    const float* ub1 = (const float*)d_in[5];
    const float* uw2 = (const float*)d_in[6];
    const float* ub2 = (const float*)d_in[7];
    const float* tw0 = (const float*)d_in[8];
    const float* tb0 = (const float*)d_in[9];
    const float* tw1 = (const float*)d_in[10];
    const float* tb1 = (const float*)d_in[11];
    const float* tw2 = (const float*)d_in[12];
    const float* tb2 = (const float*)d_in[13];
    const float* head_q = (const float*)d_in[14];
    const float* fw1 = (const float*)d_in[15];
    const float* fb1 = (const float*)d_in[16];
    const float* fw2 = (const float*)d_in[17];
    const float* fb2 = (const float*)d_in[18];
    float* out = (float*)d_out;

    cudaFuncSetAttribute(stageE_k,
                         cudaFuncAttributeMaxDynamicSharedMemorySize,
                         SMEM_E_BYTES);

    // Encoders + qb in one launch (385 blocks x 256 threads, 8 rows/block)
    enc_fused_kernel<<<385, 256>>>(uav_feat, task_feat,
                                   uw0, ub0, uw1, ub1, uw2, ub2,
                                   tw0, tb0, tw1, tb1, tw2, tb2,
                                   head_q, fw1, fb1);

    // Stage E over 4 d-quadrants x 64 (b,h)
    dim3 grid(4, B_ * H_);
    stageE_k<<<grid, 512, SMEM_E_BYTES>>>(fw2);

    // Combine partials + bias
    combine_kernel<<<(B_ * H_ * U_ * T_ / 4) / 256, 256>>>(out, fb2);
}